// round 4
// baseline (speedup 1.0000x reference)
#include <cuda_runtime.h>
#include <cstdint>

#define PB 64
#define PS 4096
#define PD 256
#define PL 16

#define TM 64
#define TN 128
#define KC 64
#define NCHUNK (PD / KC)   // 4
#define THREADS 128

// tile rows: 128 bytes = [hi 64B | lo 64B], 16B-chunk XOR swizzle by (row&7)
#define A_SZ (TM * 128)            // 8192
#define B_SZ (TN * 128)            // 16384
#define STAGE (A_SZ + B_SZ)        // 24576

__device__ __forceinline__ uint32_t smem_u32(const void* p) {
    uint32_t a;
    asm("{ .reg .u64 t; cvta.to.shared.u64 t, %1; cvt.u32.u64 %0, t; }"
        : "=r"(a) : "l"(p));
    return a;
}

#define LDSM4(R0, R1, R2, R3, A)                                             \
    asm volatile("ldmatrix.sync.aligned.m8n8.x4.shared.b16 {%0,%1,%2,%3}, [%4];" \
                 : "=r"(R0), "=r"(R1), "=r"(R2), "=r"(R3) : "r"(A))

__device__ __forceinline__ void imma(int* d, const uint32_t* a, const uint32_t* b) {
    asm volatile(
        "mma.sync.aligned.m16n8k32.row.col.s32.s8.s8.s32 "
        "{%0,%1,%2,%3}, {%4,%5,%6,%7}, {%8,%9}, {%0,%1,%2,%3};"
        : "+r"(d[0]), "+r"(d[1]), "+r"(d[2]), "+r"(d[3])
        : "r"(a[0]), "r"(a[1]), "r"(a[2]), "r"(a[3]), "r"(b[0]), "r"(b[1]));
}

__device__ __forceinline__ void sts64(uint32_t addr, uint32_t a, uint32_t b) {
    asm volatile("st.shared.v2.b32 [%0], {%1, %2};" :: "r"(addr), "r"(a), "r"(b));
}

// quantize 4 floats: j = round(x*scale) + 128; hi byte = j>>8 (int8),
// lo byte = (j&0xFF)-128 (= byte ^ 0x80). x*scale == 256*hi + lo (exact ints).
__device__ __forceinline__ void quant4(float4 v, float s, uint32_t& hb, uint32_t& lb) {
    int j0 = __float2int_rn(fmaf(v.x, s, 128.f));
    int j1 = __float2int_rn(fmaf(v.y, s, 128.f));
    int j2 = __float2int_rn(fmaf(v.z, s, 128.f));
    int j3 = __float2int_rn(fmaf(v.w, s, 128.f));
    uint32_t u = __byte_perm(j0, j1, 0x0051);
    uint32_t w = __byte_perm(j2, j3, 0x0051);
    hb = __byte_perm(u, w, 0x5410);
    u = __byte_perm(j0, j1, 0x0040);
    w = __byte_perm(j2, j3, 0x0040);
    lb = __byte_perm(u, w, 0x5410) ^ 0x80808080u;
}

__global__ __launch_bounds__(THREADS, 2)
void mm_imma_kernel(const float* __restrict__ X,
                    const float* __restrict__ Wmap,
                    const int* __restrict__ pid,
                    float* __restrict__ out) {
    __shared__ __align__(128) uint8_t tiles[2][STAGE];

    const int b  = blockIdx.z;
    const int s0 = blockIdx.x * TM;
    const int e0 = blockIdx.y * TN;
    const int tid = threadIdx.x;
    const int wid = tid >> 5;
    const int lid = tid & 31;

    int lang = pid[b];
    const float* __restrict__ Xb = X   + ((size_t)b * PS + s0) * PD;
    float* __restrict__       Ob = out + ((size_t)b * PS + s0) * PD;

    // ---------------- passthrough ----------------
    if (lang < 0) {
        #pragma unroll 4
        for (int it = 0; it < 16; ++it) {
            int idx = it * THREADS + tid;   // 2048 float4 in 64x128 tile
            int r = idx >> 5;
            int c = idx & 31;
            ((float4*)(Ob + (size_t)r * PD + e0))[c] =
                ((const float4*)(Xb + (size_t)r * PD + e0))[c];
        }
        return;
    }
    if (lang >= PL) lang = PL - 1;
    const float* __restrict__ Wl = Wmap + (size_t)lang * PD * PD + (size_t)e0 * PD;

    const uint32_t sA0 = smem_u32(&tiles[0][0]);
    const uint32_t sB0 = sA0 + A_SZ;

    const int nw = wid * 32;       // warp's N offset (warp grid 1x4)

    int hh[4][4][4], cx[4][4][4];
    #pragma unroll
    for (int f = 0; f < 4; ++f)
        #pragma unroll
        for (int g = 0; g < 4; ++g)
            #pragma unroll
            for (int q = 0; q < 4; ++q) { hh[f][g][q] = 0; cx[f][g][q] = 0; }

    // ---- converter: load chunk (kb) of A and B, quantize, store to stage ----
    auto load_store = [&](int kb, int stg) {
        const uint32_t sa = sA0 + stg * STAGE;
        const uint32_t sb = sB0 + stg * STAGE;
        // A: 64 rows x 8 k8-groups
        #pragma unroll
        for (int it = 0; it < 4; ++it) {
            int idx = it * THREADS + tid;   // 0..511
            int r  = idx >> 3;
            int k8 = idx & 7;
            const float* p = Xb + (size_t)r * PD + kb + k8 * 8;
            float4 v0 = ((const float4*)p)[0];
            float4 v1 = ((const float4*)p)[1];
            uint32_t h0, l0, h1, l1;
            quant4(v0, 4096.f, h0, l0);
            quant4(v1, 4096.f, h1, l1);
            uint32_t c = (uint32_t)(k8 >> 1);
            uint32_t off = r * 128 + ((c ^ (r & 7)) << 4) + (k8 & 1) * 8;
            sts64(sa + off, h0, h1);
            sts64((sa + off) ^ 64, l0, l1);
        }
        // B: 128 rows x 8 k8-groups
        #pragma unroll
        for (int it = 0; it < 8; ++it) {
            int idx = it * THREADS + tid;   // 0..1023
            int r  = idx >> 3;
            int k8 = idx & 7;
            const float* p = Wl + (size_t)r * PD + kb + k8 * 8;
            float4 v0 = ((const float4*)p)[0];
            float4 v1 = ((const float4*)p)[1];
            uint32_t h0, l0, h1, l1;
            quant4(v0, 65536.f, h0, l0);
            quant4(v1, 65536.f, h1, l1);
            uint32_t c = (uint32_t)(k8 >> 1);
            uint32_t off = r * 128 + ((c ^ (r & 7)) << 4) + (k8 & 1) * 8;
            sts64(sb + off, h0, h1);
            sts64((sb + off) ^ 64, l0, l1);
        }
    };

    // ---- MMA over one stage (2 k32 steps) ----
    auto do_mma = [&](int stg) {
        const uint32_t sa = sA0 + stg * STAGE;
        const uint32_t sb = sB0 + stg * STAGE;
        #pragma unroll
        for (int s = 0; s < 2; ++s) {
            uint32_t ah[4][4], al[4][4];
            #pragma unroll
            for (int f = 0; f < 4; ++f) {
                int r = f * 16 + (lid & 15);
                uint32_t c = (uint32_t)(s * 2 + (lid >> 4));
                uint32_t ad = sa + r * 128 + ((c ^ (r & 7)) << 4);
                LDSM4(ah[f][0], ah[f][1], ah[f][2], ah[f][3], ad);
                LDSM4(al[f][0], al[f][1], al[f][2], al[f][3], ad ^ 64);
            }
            uint32_t bh[4][2], bl[4][2];
            #pragma unroll
            for (int g2 = 0; g2 < 2; ++g2) {
                int r = nw + g2 * 16 + (lid & 7) + ((lid >> 4) << 3);
                uint32_t c = (uint32_t)(s * 2 + ((lid >> 3) & 1));
                uint32_t bd = sb + r * 128 + ((c ^ (r & 7)) << 4);
                LDSM4(bh[2 * g2][0], bh[2 * g2][1],
                      bh[2 * g2 + 1][0], bh[2 * g2 + 1][1], bd);
                LDSM4(bl[2 * g2][0], bl[2 * g2][1],
                      bl[2 * g2 + 1][0], bl[2 * g2 + 1][1], bd ^ 64);
            }
            #pragma unroll
            for (int f = 0; f < 4; ++f)
                #pragma unroll
                for (int g = 0; g < 4; ++g) {
                    imma(hh[f][g], ah[f], bh[g]);
                    imma(cx[f][g], ah[f], bl[g]);
                    imma(cx[f][g], al[f], bh[g]);
                }
        }
    };

    load_store(0, 0);
    __syncthreads();

    #pragma unroll
    for (int c = 0; c < NCHUNK; ++c) {
        if (c + 1 < NCHUNK) load_store((c + 1) * KC, (c + 1) & 1);
        do_mma(c & 1);
        if (c + 1 < NCHUNK) __syncthreads();
    }

    // ---------------- epilogue ----------------
    // x*w = (65536*hh + 256*cx + ll)/2^28 ; drop ll
    const float c1 = 0.000244140625f;       // 2^-12
    const float c2 = 9.5367431640625e-07f;  // 2^-20
    const int tr = lid >> 2;
    const int tc = (lid & 3) * 2;
    #pragma unroll
    for (int f = 0; f < 4; ++f) {
        #pragma unroll
        for (int g = 0; g < 4; ++g) {
            float d0 = (float)hh[f][g][0] * c1 + (float)cx[f][g][0] * c2;
            float d1 = (float)hh[f][g][1] * c1 + (float)cx[f][g][1] * c2;
            float d2 = (float)hh[f][g][2] * c1 + (float)cx[f][g][2] * c2;
            float d3 = (float)hh[f][g][3] * c1 + (float)cx[f][g][3] * c2;
            int row = f * 16 + tr;
            int col = e0 + nw + g * 8 + tc;
            float* p0 = Ob + (size_t)row * PD + col;
            *(float2*)p0            = make_float2(d0, d1);
            *(float2*)(p0 + 8 * PD) = make_float2(d2, d3);
        }
    }
}

extern "C" void kernel_launch(void* const* d_in, const int* in_sizes, int n_in,
                              void* d_out, int out_size) {
    const float* X    = (const float*)d_in[0];   // right_emb (B,S,D) f32
    const float* Wmap = (const float*)d_in[1];   // mapping (L,D,D) f32
    const int*   pid  = (const int*)d_in[2];     // pair_id (B,1) i32

    dim3 grid(PS / TM, PD / TN, PB);   // (64, 2, 64) = 8192 CTAs
    mm_imma_kernel<<<grid, THREADS>>>(X, Wmap, pid, (float*)d_out);
}

// round 5
// speedup vs baseline: 4.1051x; 4.1051x over previous
#include <cuda_runtime.h>
#include <cuda_fp16.h>
#include <cstdint>

#define PB 64
#define PS 4096
#define PD 256
#define PL 16

#define TM 128
#define TN 128
#define KC 64
#define NCHUNK (PD / KC)   // 4
#define THREADS 256

// per-stage tiles: A 128 rows x 128B (64 fp16), B 128 rows x 128B
#define TILE_SZ (128 * 128)              // 16384
#define STAGE (2 * TILE_SZ)              // 32768 (A + B)
#define SMEM_BYTES (2 * STAGE)           // 65536

__device__ __forceinline__ uint32_t smem_u32(const void* p) {
    uint32_t a;
    asm("{ .reg .u64 t; cvta.to.shared.u64 t, %1; cvt.u32.u64 %0, t; }"
        : "=r"(a) : "l"(p));
    return a;
}

#define LDSM4(R0, R1, R2, R3, A)                                             \
    asm volatile("ldmatrix.sync.aligned.m8n8.x4.shared.b16 {%0,%1,%2,%3}, [%4];" \
                 : "=r"(R0), "=r"(R1), "=r"(R2), "=r"(R3) : "r"(A))

__device__ __forceinline__ void mma_f16(float* d, const uint32_t* a,
                                        const uint32_t* b) {
    asm volatile(
        "mma.sync.aligned.m16n8k16.row.col.f32.f16.f16.f32 "
        "{%0,%1,%2,%3}, {%4,%5,%6,%7}, {%8,%9}, {%0,%1,%2,%3};"
        : "+f"(d[0]), "+f"(d[1]), "+f"(d[2]), "+f"(d[3])
        : "r"(a[0]), "r"(a[1]), "r"(a[2]), "r"(a[3]), "r"(b[0]), "r"(b[1]));
}

__device__ __forceinline__ void sts64(uint32_t addr, uint32_t a, uint32_t b) {
    asm volatile("st.shared.v2.b32 [%0], {%1, %2};" :: "r"(addr), "r"(a), "r"(b));
}

// swizzled byte offset for (row, 16B-chunk c) in a 128B-row tile
__device__ __forceinline__ uint32_t swz(int row, int c) {
    return (uint32_t)(row * 128 + (((c ^ (row & 7)) << 4)));
}

__device__ __forceinline__ uint32_t cvt2(float a, float b) {
    __half2 h = __floats2half2_rn(a, b);
    return *reinterpret_cast<uint32_t*>(&h);
}

__global__ __launch_bounds__(THREADS, 2)
void mm_f16_kernel(const float* __restrict__ X,
                   const float* __restrict__ Wmap,
                   const int* __restrict__ pid,
                   float* __restrict__ out) {
    extern __shared__ char smem[];
    const int b  = blockIdx.z;
    const int s0 = blockIdx.x * TM;
    const int e0 = blockIdx.y * TN;
    const int tid = threadIdx.x;
    const int wid = tid >> 5;
    const int lid = tid & 31;

    int lang = pid[b];
    const float* __restrict__ Xb = X   + ((size_t)b * PS + s0) * PD;
    float* __restrict__       Ob = out + ((size_t)b * PS + s0) * PD;

    // ---------------- passthrough ----------------
    if (lang < 0) {
        #pragma unroll 4
        for (int i = 0; i < 16; ++i) {
            int idx = i * THREADS + tid;     // 4096 float4 in 128x128 tile
            int r = idx >> 5;
            int c = idx & 31;
            ((float4*)(Ob + (size_t)r * PD + e0))[c] =
                ((const float4*)(Xb + (size_t)r * PD + e0))[c];
        }
        return;
    }
    if (lang >= PL) lang = PL - 1;
    const float* __restrict__ Wl = Wmap + (size_t)lang * PD * PD + (size_t)e0 * PD;

    const uint32_t sb = smem_u32(smem);

    // warp layout: 2 (M) x 4 (N); warp tile 64 x 32
    const int m0 = (wid & 1) * 64;
    const int n0 = (wid >> 1) * 32;

    float acc[4][4][4];
    #pragma unroll
    for (int f = 0; f < 4; ++f)
        #pragma unroll
        for (int g = 0; g < 4; ++g)
            #pragma unroll
            for (int q = 0; q < 4; ++q) acc[f][g][q] = 0.f;

    // ---- produce one chunk into a stage ----
    auto produce = [&](int kb, int stg) {
        const uint32_t sa = sb + stg * STAGE;
        const uint32_t sw = sa + TILE_SZ;
        #pragma unroll
        for (int i = 0; i < 8; ++i) {
            int idx = i * THREADS + tid;        // 2048 float4
            int r  = idx >> 4;                  // 0..127
            int k4 = (idx & 15) * 4;            // 0..60
            float4 v = *(const float4*)(Xb + (size_t)r * PD + kb + k4);
            uint32_t off = swz(r, k4 >> 3) + ((k4 & 7) << 1);
            sts64(sa + off, cvt2(v.x, v.y), cvt2(v.z, v.w));
        }
        #pragma unroll
        for (int i = 0; i < 8; ++i) {
            int idx = i * THREADS + tid;
            int r  = idx >> 4;
            int k4 = (idx & 15) * 4;
            float4 v = *(const float4*)(Wl + (size_t)r * PD + kb + k4);
            uint32_t off = swz(r, k4 >> 3) + ((k4 & 7) << 1);
            sts64(sw + off, cvt2(v.x, v.y), cvt2(v.z, v.w));
        }
    };

    // ---- consume one stage: 4 k16 steps ----
    auto consume = [&](int stg) {
        const uint32_t sa = sb + stg * STAGE;
        const uint32_t sw = sa + TILE_SZ;
        #pragma unroll
        for (int ks = 0; ks < 4; ++ks) {
            uint32_t ah[4][4];
            #pragma unroll
            for (int f = 0; f < 4; ++f) {
                int r = m0 + f * 16 + (lid & 15);
                int c = ks * 2 + (lid >> 4);
                LDSM4(ah[f][0], ah[f][1], ah[f][2], ah[f][3], sa + swz(r, c));
            }
            uint32_t bh[4][2];
            #pragma unroll
            for (int g2 = 0; g2 < 2; ++g2) {
                int r = n0 + g2 * 16 + (lid & 7) + ((lid >> 4) << 3);
                int c = ks * 2 + ((lid >> 3) & 1);
                LDSM4(bh[2 * g2][0], bh[2 * g2][1],
                      bh[2 * g2 + 1][0], bh[2 * g2 + 1][1], sw + swz(r, c));
            }
            #pragma unroll
            for (int f = 0; f < 4; ++f)
                #pragma unroll
                for (int g = 0; g < 4; ++g)
                    mma_f16(acc[f][g], ah[f], bh[g]);
        }
    };

    produce(0, 0);
    __syncthreads();

    #pragma unroll
    for (int c = 0; c < NCHUNK; ++c) {
        if (c + 1 < NCHUNK) produce((c + 1) * KC, (c + 1) & 1);
        consume(c & 1);
        if (c + 1 < NCHUNK) __syncthreads();
    }

    // ---------------- epilogue ----------------
    const int tr = lid >> 2;          // 0..7
    const int tc = (lid & 3) * 2;     // 0,2,4,6
    #pragma unroll
    for (int f = 0; f < 4; ++f) {
        #pragma unroll
        for (int g = 0; g < 4; ++g) {
            int row = m0 + f * 16 + tr;
            int col = e0 + n0 + g * 8 + tc;
            float* p0 = Ob + (size_t)row * PD + col;
            *(float2*)p0            = make_float2(acc[f][g][0], acc[f][g][1]);
            *(float2*)(p0 + 8 * PD) = make_float2(acc[f][g][2], acc[f][g][3]);
        }
    }
}

extern "C" void kernel_launch(void* const* d_in, const int* in_sizes, int n_in,
                              void* d_out, int out_size) {
    const float* X    = (const float*)d_in[0];   // right_emb (B,S,D) f32
    const float* Wmap = (const float*)d_in[1];   // mapping (L,D,D) f32
    const int*   pid  = (const int*)d_in[2];     // pair_id (B,1) i32

    cudaFuncSetAttribute(mm_f16_kernel,
                         cudaFuncAttributeMaxDynamicSharedMemorySize, SMEM_BYTES);
    dim3 grid(PS / TM, PD / TN, PB);   // (32, 2, 64)
    mm_f16_kernel<<<grid, THREADS, SMEM_BYTES>>>(X, Wmap, pid, (float*)d_out);
}

// round 6
// speedup vs baseline: 4.4309x; 1.0794x over previous
#include <cuda_runtime.h>
#include <cuda_fp16.h>
#include <cstdint>

#define PB 64
#define PS 4096
#define PD 256
#define PL 16

#define TM 128
#define TN 256
#define KC 64
#define NCHUNK (PD / KC)   // 4
#define THREADS 256

// per-stage tiles: A 128 rows x 128B (64 fp16), B 256 rows x 128B
#define A_SZ (128 * 128)                 // 16384
#define B_SZ (256 * 128)                 // 32768
#define STAGE (A_SZ + B_SZ)              // 49152
#define SMEM_BYTES (2 * STAGE)           // 98304

__device__ __forceinline__ uint32_t smem_u32(const void* p) {
    uint32_t a;
    asm("{ .reg .u64 t; cvta.to.shared.u64 t, %1; cvt.u32.u64 %0, t; }"
        : "=r"(a) : "l"(p));
    return a;
}

#define LDSM4(R0, R1, R2, R3, A)                                             \
    asm volatile("ldmatrix.sync.aligned.m8n8.x4.shared.b16 {%0,%1,%2,%3}, [%4];" \
                 : "=r"(R0), "=r"(R1), "=r"(R2), "=r"(R3) : "r"(A))

__device__ __forceinline__ void mma_f16(float* d, const uint32_t* a,
                                        const uint32_t* b) {
    asm volatile(
        "mma.sync.aligned.m16n8k16.row.col.f32.f16.f16.f32 "
        "{%0,%1,%2,%3}, {%4,%5,%6,%7}, {%8,%9}, {%0,%1,%2,%3};"
        : "+f"(d[0]), "+f"(d[1]), "+f"(d[2]), "+f"(d[3])
        : "r"(a[0]), "r"(a[1]), "r"(a[2]), "r"(a[3]), "r"(b[0]), "r"(b[1]));
}

__device__ __forceinline__ void sts64(uint32_t addr, uint32_t a, uint32_t b) {
    asm volatile("st.shared.v2.b32 [%0], {%1, %2};" :: "r"(addr), "r"(a), "r"(b));
}

// swizzled byte offset for (row, 16B-chunk c) in a 128B-row tile
__device__ __forceinline__ uint32_t swz(int row, int c) {
    return (uint32_t)(row * 128 + (((c ^ (row & 7)) << 4)));
}

__device__ __forceinline__ uint32_t cvt2(float a, float b) {
    __half2 h = __floats2half2_rn(a, b);
    return *reinterpret_cast<uint32_t*>(&h);
}

__global__ __launch_bounds__(THREADS, 1)
void mm_f16w_kernel(const float* __restrict__ X,
                    const float* __restrict__ Wmap,
                    const int* __restrict__ pid,
                    float* __restrict__ out) {
    extern __shared__ char smem[];
    const int b  = blockIdx.z;
    const int s0 = blockIdx.x * TM;
    const int tid = threadIdx.x;
    const int wid = tid >> 5;
    const int lid = tid & 31;

    int lang = pid[b];
    const float* __restrict__ Xb = X   + ((size_t)b * PS + s0) * PD;
    float* __restrict__       Ob = out + ((size_t)b * PS + s0) * PD;

    // ---------------- passthrough ----------------
    if (lang < 0) {
        #pragma unroll 8
        for (int i = 0; i < 32; ++i) {
            int idx = i * THREADS + tid;     // 8192 float4 in 128x256 tile
            ((float4*)Ob)[idx] = ((const float4*)Xb)[idx];
        }
        return;
    }
    if (lang >= PL) lang = PL - 1;
    const float* __restrict__ Wl = Wmap + (size_t)lang * PD * PD;

    const uint32_t sb = smem_u32(smem);

    // warp layout: 2 (M) x 4 (N); warp tile 64 x 64
    const int m0 = (wid & 1) * 64;
    const int n0 = (wid >> 1) * 64;

    float acc[4][8][4];
    #pragma unroll
    for (int f = 0; f < 4; ++f)
        #pragma unroll
        for (int g = 0; g < 8; ++g)
            #pragma unroll
            for (int q = 0; q < 4; ++q) acc[f][g][q] = 0.f;

    // ---- produce one chunk into a stage ----
    auto produce = [&](int kb, int stg) {
        const uint32_t sa = sb + stg * STAGE;
        const uint32_t sw = sa + A_SZ;
        #pragma unroll
        for (int i = 0; i < 8; ++i) {
            int idx = i * THREADS + tid;        // 2048 float4 (A: 128 rows)
            int r  = idx >> 4;
            int k4 = (idx & 15) * 4;
            float4 v = *(const float4*)(Xb + (size_t)r * PD + kb + k4);
            uint32_t off = swz(r, k4 >> 3) + ((k4 & 7) << 1);
            sts64(sa + off, cvt2(v.x, v.y), cvt2(v.z, v.w));
        }
        #pragma unroll
        for (int i = 0; i < 16; ++i) {
            int idx = i * THREADS + tid;        // 4096 float4 (B: 256 rows)
            int r  = idx >> 4;
            int k4 = (idx & 15) * 4;
            float4 v = *(const float4*)(Wl + (size_t)r * PD + kb + k4);
            uint32_t off = swz(r, k4 >> 3) + ((k4 & 7) << 1);
            sts64(sw + off, cvt2(v.x, v.y), cvt2(v.z, v.w));
        }
    };

    // ---- consume one stage: 4 k16 steps ----
    auto consume = [&](int stg) {
        const uint32_t sa = sb + stg * STAGE;
        const uint32_t sw = sa + A_SZ;
        #pragma unroll
        for (int ks = 0; ks < 4; ++ks) {
            uint32_t ah[4][4];
            #pragma unroll
            for (int f = 0; f < 4; ++f) {
                int r = m0 + f * 16 + (lid & 15);
                int c = ks * 2 + (lid >> 4);
                LDSM4(ah[f][0], ah[f][1], ah[f][2], ah[f][3], sa + swz(r, c));
            }
            uint32_t bh[8][2];
            #pragma unroll
            for (int g2 = 0; g2 < 4; ++g2) {
                int r = n0 + g2 * 16 + (lid & 7) + ((lid >> 4) << 3);
                int c = ks * 2 + ((lid >> 3) & 1);
                LDSM4(bh[2 * g2][0], bh[2 * g2][1],
                      bh[2 * g2 + 1][0], bh[2 * g2 + 1][1], sw + swz(r, c));
            }
            #pragma unroll
            for (int f = 0; f < 4; ++f)
                #pragma unroll
                for (int g = 0; g < 8; ++g)
                    mma_f16(acc[f][g], ah[f], bh[g]);
        }
    };

    produce(0, 0);
    __syncthreads();

    #pragma unroll
    for (int c = 0; c < NCHUNK; ++c) {
        if (c + 1 < NCHUNK) produce((c + 1) * KC, (c + 1) & 1);
        consume(c & 1);
        if (c + 1 < NCHUNK) __syncthreads();
    }

    // ---------------- epilogue ----------------
    const int tr = lid >> 2;          // 0..7
    const int tc = (lid & 3) * 2;     // 0,2,4,6
    #pragma unroll
    for (int f = 0; f < 4; ++f) {
        #pragma unroll
        for (int g = 0; g < 8; ++g) {
            int row = m0 + f * 16 + tr;
            int col = n0 + g * 8 + tc;
            float* p0 = Ob + (size_t)row * PD + col;
            *(float2*)p0            = make_float2(acc[f][g][0], acc[f][g][1]);
            *(float2*)(p0 + 8 * PD) = make_float2(acc[f][g][2], acc[f][g][3]);
        }
    }
}

extern "C" void kernel_launch(void* const* d_in, const int* in_sizes, int n_in,
                              void* d_out, int out_size) {
    const float* X    = (const float*)d_in[0];   // right_emb (B,S,D) f32
    const float* Wmap = (const float*)d_in[1];   // mapping (L,D,D) f32
    const int*   pid  = (const int*)d_in[2];     // pair_id (B,1) i32

    cudaFuncSetAttribute(mm_f16w_kernel,
                         cudaFuncAttributeMaxDynamicSharedMemorySize, SMEM_BYTES);
    dim3 grid(PS / TM, 1, PB);   // (32, 1, 64) = 2048 CTAs
    mm_f16w_kernel<<<grid, THREADS, SMEM_BYTES>>>(X, Wmap, pid, (float*)d_out);
}